// round 3
// baseline (speedup 1.0000x reference)
#include <cuda_runtime.h>
#include <cstdint>

typedef unsigned long long u64;

// ---------------- problem constants ----------------
#define TSEQ 16384
#define HID  128
#define GROWS 512   // 4*HID
#define NB   8      // h ring-buffer depth
#define HPAD 68     // padded half-h stride (272B -> bank-shifted halves)

// ---------------- scratch (device globals; no allocation) ----------------
__device__ float g_pre[(size_t)TSEQ * GROWS];
__device__ float g_h1[(size_t)TSEQ * HID];
__device__ float g_h2[(size_t)TSEQ * HID];

// ---------------- small helpers ----------------
__device__ __forceinline__ uint32_t smem_u32(const void* p) {
    return (uint32_t)__cvta_generic_to_shared(p);
}
__device__ __forceinline__ u64 ffma2(u64 a, u64 b, u64 c) {
    u64 d;
    asm("fma.rn.f32x2 %0, %1, %2, %3;" : "=l"(d) : "l"(a), "l"(b), "l"(c));
    return d;
}
__device__ __forceinline__ u64 fadd2(u64 a, u64 b) {
    u64 d;
    asm("add.rn.f32x2 %0, %1, %2;" : "=l"(d) : "l"(a), "l"(b));
    return d;
}
__device__ __forceinline__ float2 unpack2(u64 a) {
    float2 r;
    asm("mov.b64 {%0, %1}, %2;" : "=f"(r.x), "=f"(r.y) : "l"(a));
    return r;
}
__device__ __forceinline__ float fast_sigmoid(float x) {
    return __fdividef(1.f, 1.f + __expf(-x));
}
__device__ __forceinline__ float fast_tanh(float x) {
    return 1.f - __fdividef(2.f, __expf(2.f * x) + 1.f);
}
__device__ __forceinline__ void mbar_wait_cluster(uint32_t addr, unsigned parity) {
    asm volatile(
        "{\n\t"
        ".reg .pred P1;\n\t"
        "WAIT_%=:\n\t"
        "mbarrier.try_wait.parity.acquire.cluster.shared::cta.b64 P1, [%0], %1, 0x989680;\n\t"
        "@P1 bra DONE_%=;\n\t"
        "bra WAIT_%=;\n\t"
        "DONE_%=:\n\t"
        "}"
        :: "r"(addr), "r"(parity) : "memory");
}

// ============================================================================
// Sequential LSTM scan: 4-CTA cluster, W_hh in registers.
// CTA rank r owns hidden units j in [32r, 32r+32).
// Thread layout (within a warp): lane = ul*8 + gate*2 + kh
//   ul   = unit-within-warp (4 units/warp, 8 warps -> 32 units/CTA)
//   gate = 0..3 (i,f,g,o), kh = K-half (cols [64kh, 64kh+64))
// Per step:
//   - all threads: 64-col partial dot (32 f32x2 FMAs, weights in regs)
//   - shfl_xor(1): combine k-halves; + pre; activation
//   - 4 shfls gather i,f,g,o to owner lane (lane%8==0)
//   - owner: c/h update; st.shared::cluster h to all 4 CTAs' ring slot
//     (s+1)%8 + release-arrive on all 4 full-bars (count 128 each)
//   - everyone waits local full-bar to enter next step
// Ring reuse safety: one __syncthreads per 4 steps certifies local reads;
// tid1 relays a cluster-wide rfree signal (count 4); everyone consumes the
// signal one super-step later (>=2 super-steps of slack vs the 8-deep ring).
// ============================================================================
__global__ void __cluster_dims__(4, 1, 1) __launch_bounds__(256, 1)
lstm_scan_kernel(const float* __restrict__ W_hh, int layer)
{
    __shared__ __align__(16) float h_sm[NB][2][HPAD];
    __shared__ __align__(8) u64 bar_full[4];
    __shared__ __align__(8) u64 bar_rfree;

    const float* __restrict__ pre = g_pre;
    float* __restrict__ hout = layer ? g_h2 : g_h1;

    const int tid  = threadIdx.x;
    const int lane = tid & 31;
    const int warp = tid >> 5;
    unsigned rank;
    asm("mov.u32 %0, %%cluster_ctarank;" : "=r"(rank));

    const int kh   = lane & 1;
    const int gate = (lane >> 1) & 3;
    const int uc   = warp * 4 + (lane >> 3);   // unit within CTA [0,32)
    const int j    = (int)rank * 32 + uc;      // global hidden unit
    const int row  = gate * HID + j;           // gate row [0,512)

    // ---- this thread's 64 weights (half a row) as 32 f32x2 regs
    u64 w[32];
    {
        const ulonglong2* ws =
            reinterpret_cast<const ulonglong2*>(W_hh + (size_t)row * HID + kh * 64);
#pragma unroll
        for (int i = 0; i < 16; i++) {
            ulonglong2 v = ws[i];
            w[2 * i]     = v.x;
            w[2 * i + 1] = v.y;
        }
    }

    // ---- init: zero ring slot 0 (h_0 = 0), init barriers
    if (tid < 2 * HPAD) ((float*)h_sm)[tid] = 0.f;
    const uint32_t fullb = smem_u32(bar_full);
    const uint32_t rfb   = smem_u32(&bar_rfree);
    if (tid == 0) {
#pragma unroll
        for (int b = 0; b < 4; b++)
            asm volatile("mbarrier.init.shared.b64 [%0], %1;"
                         :: "r"(fullb + (unsigned)(b * 8)), "r"(128u));
        asm volatile("mbarrier.init.shared.b64 [%0], %1;" :: "r"(rfb), "r"(4u));
        // pre-signal full[0] so the s=0 wait passes (ring slot 0 pre-zeroed)
        asm volatile("mbarrier.arrive.release.cta.shared::cta.b64 _, [%0], %1;"
                     :: "r"(fullb), "r"(128u) : "memory");
        asm volatile("fence.mbarrier_init.release.cluster;" ::: "memory");
    }
    __syncthreads();
    asm volatile("barrier.cluster.arrive.aligned;" ::: "memory");
    asm volatile("barrier.cluster.wait.aligned;"   ::: "memory");

    // ---- cluster addresses of every CTA's h ring / bars
    const uint32_t hb = smem_u32(h_sm);
    uint32_t haddr[4], faddr[4], rfaddr[4];
#pragma unroll
    for (int p = 0; p < 4; p++) {
        asm("mapa.shared::cluster.u32 %0, %1, %2;" : "=r"(haddr[p])  : "r"(hb),    "r"((unsigned)p));
        asm("mapa.shared::cluster.u32 %0, %1, %2;" : "=r"(faddr[p])  : "r"(fullb), "r"((unsigned)p));
        asm("mapa.shared::cluster.u32 %0, %1, %2;" : "=r"(rfaddr[p]) : "r"(rfb),   "r"((unsigned)p));
    }

    float c = 0.f;            // cell state (owner lanes)
    unsigned mph = 0;         // super-step parity
    float pcur[4];
#pragma unroll
    for (int u = 0; u < 4; u++)
        pcur[u] = pre[(size_t)u * GROWS + row];

    const int M = TSEQ / 4;
    for (int m = 0; m < M; m++) {
        // consume read-release of super-step m-1 before overwriting ring slots
        if (m) mbar_wait_cluster(rfb, mph ^ 1u);

        // prefetch next super-step's gate inputs (hidden under ~4 steps)
        float pnx[4] = {0.f, 0.f, 0.f, 0.f};
        if (m + 1 < M) {
#pragma unroll
            for (int u = 0; u < 4; u++)
                pnx[u] = pre[(size_t)(4 * (m + 1) + u) * GROWS + row];
        }

#pragma unroll
        for (int u = 0; u < 4; u++) {
            const int s = 4 * m + u;

            // wait for h of step s (ring slot s%8) to be complete in local smem
            mbar_wait_cluster(fullb + (unsigned)((s & 3) * 8), mph);

            // ---- 64-col partial matvec (broadcast LDS.128, packed FMAs)
            const ulonglong2* hp = reinterpret_cast<const ulonglong2*>(
                (const char*)h_sm + (size_t)(((s & 7) * 2 + kh) * HPAD) * 4);
            u64 a0 = 0ull, a1 = 0ull, a2 = 0ull, a3 = 0ull;
#pragma unroll
            for (int i = 0; i < 16; i += 2) {
                ulonglong2 x = hp[i];
                ulonglong2 y = hp[i + 1];
                a0 = ffma2(w[2 * i],     x.x, a0);
                a1 = ffma2(w[2 * i + 1], x.y, a1);
                a2 = ffma2(w[2 * i + 2], y.x, a2);
                a3 = ffma2(w[2 * i + 3], y.y, a3);
            }

            // once per super-step: certify all local reads (for ring reuse)
            if (u == 3) __syncthreads();

            float2 ar = unpack2(fadd2(fadd2(a0, a1), fadd2(a2, a3)));
            float d = ar.x + ar.y;
            d += __shfl_xor_sync(0xffffffffu, d, 1);   // combine k-halves
            float gval = d + pcur[u];
            float av = (gate == 2) ? fast_tanh(gval) : fast_sigmoid(gval);

            // gather i,f,g,o of this unit to the owner lane (all intra-warp)
            const unsigned bl = (unsigned)(lane & ~7);
            float iv = __shfl_sync(0xffffffffu, av, bl);
            float fv = __shfl_sync(0xffffffffu, av, bl + 2);
            float gv = __shfl_sync(0xffffffffu, av, bl + 4);
            float ov = __shfl_sync(0xffffffffu, av, bl + 6);

            if ((lane & 7) == 0) {
                c = fv * c + iv * gv;
                float hv = ov * fast_tanh(c);

                const unsigned soff =
                    (unsigned)(((((s + 1) & 7) * 2 + (j >> 6)) * HPAD + (j & 63)) * 4);
                const unsigned boff = (unsigned)(((s + 1) & 3) * 8);
#pragma unroll
                for (int p = 0; p < 4; p++) {
                    asm volatile("st.shared::cluster.f32 [%0], %1;"
                                 :: "r"(haddr[p] + soff), "f"(hv) : "memory");
                    asm volatile(
                        "mbarrier.arrive.release.cluster.shared::cluster.b64 _, [%0];"
                        :: "r"(faddr[p] + boff) : "memory");
                }
                hout[(size_t)s * HID + j] = hv;   // off critical path
            }
        }

        // relay "this CTA finished reading steps 4m..4m+3" to all CTAs
        if (tid == 1) {
#pragma unroll
            for (int p = 0; p < 4; p++)
                asm volatile(
                    "mbarrier.arrive.release.cluster.shared::cluster.b64 _, [%0];"
                    :: "r"(rfaddr[p]) : "memory");
        }

#pragma unroll
        for (int u = 0; u < 4; u++) pcur[u] = pnx[u];
        mph ^= 1u;
    }

    asm volatile("barrier.cluster.arrive.aligned;" ::: "memory");
    asm volatile("barrier.cluster.wait.aligned;"   ::: "memory");
}

// ============================================================================
// Input projection: g_pre[t, r] = (ba[r] + bb[r]) + sum_k A[t,k] * W[r,k]
// ============================================================================
template <int K>
__global__ void __launch_bounds__(512)
addmm_kernel(const float* __restrict__ Aext, int useH1,
             const float* __restrict__ W,
             const float* __restrict__ ba, const float* __restrict__ bb)
{
    constexpr int BT = 8;
    const float* __restrict__ A = useH1 ? g_h1 : Aext;
    __shared__ float As[BT * K];

    const int t0 = blockIdx.x * BT;
    for (int idx = threadIdx.x; idx < BT * K; idx += 512)
        As[idx] = A[(size_t)t0 * K + idx];
    __syncthreads();

    const int r = threadIdx.x;
    float bias = ba[r] + bb[r];
    float acc[BT];
#pragma unroll
    for (int i = 0; i < BT; i++) acc[i] = bias;

    const float* wr = W + (size_t)r * K;
#pragma unroll 2
    for (int k = 0; k < K; k++) {
        float wv = __ldg(wr + k);
#pragma unroll
        for (int i = 0; i < BT; i++) acc[i] = fmaf(wv, As[i * K + k], acc[i]);
    }
#pragma unroll
    for (int i = 0; i < BT; i++)
        g_pre[(size_t)(t0 + i) * GROWS + r] = acc[i];
}

// ============================================================================
// Final FC: out[t, o] = fc_b[o] + sum_k g_h2[t,k] * fc_W[o,k]   (OUT = 5)
// ============================================================================
__global__ void __launch_bounds__(256)
fc_kernel(const float* __restrict__ fcW, const float* __restrict__ fcb,
          float* __restrict__ out)
{
    __shared__ float Ws[5 * HID];
    __shared__ float bs[5];
    for (int idx = threadIdx.x; idx < 5 * HID; idx += 256) Ws[idx] = fcW[idx];
    if (threadIdx.x < 5) bs[threadIdx.x] = fcb[threadIdx.x];
    __syncthreads();

    const int t = blockIdx.x * 256 + threadIdx.x;
    float acc[5];
#pragma unroll
    for (int o = 0; o < 5; o++) acc[o] = bs[o];

    const float4* hp = reinterpret_cast<const float4*>(&g_h2[(size_t)t * HID]);
#pragma unroll 4
    for (int k4 = 0; k4 < HID / 4; k4++) {
        float4 h = hp[k4];
#pragma unroll
        for (int o = 0; o < 5; o++) {
            acc[o] = fmaf(h.x, Ws[o * HID + 4 * k4 + 0], acc[o]);
            acc[o] = fmaf(h.y, Ws[o * HID + 4 * k4 + 1], acc[o]);
            acc[o] = fmaf(h.z, Ws[o * HID + 4 * k4 + 2], acc[o]);
            acc[o] = fmaf(h.w, Ws[o * HID + 4 * k4 + 3], acc[o]);
        }
    }
#pragma unroll
    for (int o = 0; o < 5; o++) out[(size_t)t * 5 + o] = acc[o];
}

// ============================================================================
// kernel_launch: pre1 GEMM -> scan L1 -> pre2 GEMM -> scan L2 -> FC
// ============================================================================
extern "C" void kernel_launch(void* const* d_in, const int* in_sizes, int n_in,
                              void* d_out, int out_size)
{
    (void)in_sizes; (void)n_in; (void)out_size;

    const float* x     = (const float*)d_in[0];
    const float* W_ih1 = (const float*)d_in[1];
    const float* W_hh1 = (const float*)d_in[2];
    const float* b_ih1 = (const float*)d_in[3];
    const float* b_hh1 = (const float*)d_in[4];
    const float* W_ih2 = (const float*)d_in[5];
    const float* W_hh2 = (const float*)d_in[6];
    const float* b_ih2 = (const float*)d_in[7];
    const float* b_hh2 = (const float*)d_in[8];
    const float* fc_W  = (const float*)d_in[9];
    const float* fc_b  = (const float*)d_in[10];
    float* out = (float*)d_out;

    addmm_kernel<50><<<TSEQ / 8, 512>>>(x, 0, W_ih1, b_ih1, b_hh1);
    lstm_scan_kernel<<<4, 256>>>(W_hh1, 0);
    addmm_kernel<128><<<TSEQ / 8, 512>>>(nullptr, 1, W_ih2, b_ih2, b_hh2);
    lstm_scan_kernel<<<4, 256>>>(W_hh2, 1);
    fc_kernel<<<TSEQ / 256, 256>>>(fc_W, fc_b, out);
}

// round 4
// speedup vs baseline: 1.5272x; 1.5272x over previous
#include <cuda_runtime.h>
#include <cstdint>

typedef unsigned long long u64;

// ---------------- problem constants ----------------
#define TSEQ 16384
#define HID  128
#define GROWS 512   // 4*HID
#define CR   96     // W_hh columns held in registers (per row)
#define CS   32     // W_hh columns held in shared memory

// ---------------- scratch (device globals; no allocation) ----------------
__device__ float g_pre[(size_t)TSEQ * GROWS];
__device__ float g_h1[(size_t)TSEQ * HID];
__device__ float g_h2[(size_t)TSEQ * HID];

// ---------------- helpers ----------------
__device__ __forceinline__ u64 ffma2(u64 a, u64 b, u64 c) {
    u64 d;
    asm("fma.rn.f32x2 %0, %1, %2, %3;" : "=l"(d) : "l"(a), "l"(b), "l"(c));
    return d;
}
__device__ __forceinline__ u64 fadd2(u64 a, u64 b) {
    u64 d;
    asm("add.rn.f32x2 %0, %1, %2;" : "=l"(d) : "l"(a), "l"(b));
    return d;
}
__device__ __forceinline__ float2 unpack2(u64 a) {
    float2 r;
    asm("mov.b64 {%0, %1}, %2;" : "=f"(r.x), "=f"(r.y) : "l"(a));
    return r;
}
__device__ __forceinline__ float fast_sigmoid(float x) {
    return __fdividef(1.f, 1.f + __expf(-x));
}
__device__ __forceinline__ float fast_tanh(float x) {
    return 1.f - __fdividef(2.f, __expf(2.f * x) + 1.f);
}

// ============================================================================
// Single-CTA LSTM scan. 256 threads, one SM, zero cross-SM traffic.
//   thread: j = tid>>1 (hidden unit), p = tid&1
//   rows:   r0 = (2p)*HID + j, r1 = (2p+1)*HID + j
//           p=0 -> gates i,f ; p=1 -> gates g,o  (PyTorch order i,f,g,o)
// Weights: cols [0,96) in registers (48 f32x2 per row),
//          cols [96,128) in SMEM quad layout WQ[q][row][4] (64 KB).
// Per step:
//   dot (h broadcast LDS.128 + packed FMAs) -> activations ->
//   shfl_xor(1) pair exchange -> even lanes update c,h ->
//   write h double-buffer + stream h to global -> one __syncthreads.
// ============================================================================
__global__ void __launch_bounds__(256, 1)
lstm_scan_kernel(const float* __restrict__ W_hh, int layer)
{
    extern __shared__ __align__(16) char smem_raw[];
    // [0, 64KB): WQ as ulonglong2 array: index (q<<9)+row -> 4 floats (cols 96+4q..+3)
    ulonglong2* WQ = reinterpret_cast<ulonglong2*>(smem_raw);
    // [64KB, +1KB): h double buffer
    float* hbuf = reinterpret_cast<float*>(smem_raw + (size_t)GROWS * CS * 4);

    const float* __restrict__ pre = g_pre;
    float* __restrict__ hout = layer ? g_h2 : g_h1;

    const int tid = threadIdx.x;
    const int p   = tid & 1;
    const int j   = tid >> 1;
    const int r0  = (2 * p) * HID + j;
    const int r1  = (2 * p + 1) * HID + j;

    // ---- stage SMEM-resident weight columns [96,128) (quad layout)
    for (int idx = tid; idx < GROWS * (CS / 4); idx += 256) {
        const int q   = idx >> 9;          // quad 0..7
        const int row = idx & 511;
        const float4 v = *reinterpret_cast<const float4*>(
            W_hh + (size_t)row * HID + CR + 4 * q);
        reinterpret_cast<float4*>(WQ)[idx] = v;
    }

    // ---- register-resident weight columns [0,96): 48 f32x2 per row
    u64 w0[CR / 2], w1[CR / 2];
    {
        const ulonglong2* ws0 = reinterpret_cast<const ulonglong2*>(W_hh + (size_t)r0 * HID);
        const ulonglong2* ws1 = reinterpret_cast<const ulonglong2*>(W_hh + (size_t)r1 * HID);
#pragma unroll
        for (int i = 0; i < CR / 4; i++) {
            ulonglong2 a = ws0[i];
            w0[2 * i] = a.x; w0[2 * i + 1] = a.y;
            ulonglong2 b = ws1[i];
            w1[2 * i] = b.x; w1[2 * i + 1] = b.y;
        }
    }

    // ---- init h double buffer
    if (tid < HID) { hbuf[tid] = 0.f; hbuf[HID + tid] = 0.f; }
    __syncthreads();

    float c = 0.f;                                  // cell state (even lanes)
    float p0 = pre[r0], p1 = pre[r1];               // step-0 gate inputs

    for (int s = 0; s < TSEQ; s++) {
        const int cur = s & 1;

        // prefetch next step's gate inputs (latency hidden under the dot)
        float p0n = 0.f, p1n = 0.f;
        if (s + 1 < TSEQ) {
            const size_t b = (size_t)(s + 1) * GROWS;
            p0n = pre[b + r0];
            p1n = pre[b + r1];
        }

        // ---- matvec: rows r0,r1 dot h  (h pairs broadcast via LDS.128)
        const ulonglong2* hv2 =
            reinterpret_cast<const ulonglong2*>(hbuf + cur * HID);
        u64 a00 = 0ull, a01 = 0ull, a10 = 0ull, a11 = 0ull;
#pragma unroll
        for (int k = 0; k < CR / 4; k++) {          // 24 iters, cols 0..95
            ulonglong2 hp = hv2[k];
            a00 = ffma2(w0[2 * k],     hp.x, a00);
            a10 = ffma2(w1[2 * k],     hp.x, a10);
            a01 = ffma2(w0[2 * k + 1], hp.y, a01);
            a11 = ffma2(w1[2 * k + 1], hp.y, a11);
        }
#pragma unroll
        for (int q = 0; q < CS / 4; q++) {          // 8 iters, cols 96..127
            ulonglong2 hp = hv2[CR / 4 + q];
            ulonglong2 wa = WQ[(q << 9) + r0];
            ulonglong2 wb = WQ[(q << 9) + r1];
            a00 = ffma2(wa.x, hp.x, a00);
            a01 = ffma2(wa.y, hp.y, a01);
            a10 = ffma2(wb.x, hp.x, a10);
            a11 = ffma2(wb.y, hp.y, a11);
        }
        float2 s0 = unpack2(fadd2(a00, a01));
        float2 s1 = unpack2(fadd2(a10, a11));
        float g0 = s0.x + s0.y + p0;                // row r0 preactivation
        float g1 = s1.x + s1.y + p1;                // row r1 preactivation

        // activations: p=0 -> (i,f) both sigmoid; p=1 -> (g,o) tanh,sigmoid
        float act0 = p ? fast_tanh(g0) : fast_sigmoid(g0);
        float act1 = fast_sigmoid(g1);

        // pair exchange: even lane gets (g,o) from odd neighbor
        float x0 = __shfl_xor_sync(0xffffffffu, act0, 1);  // g (on evens)
        float x1 = __shfl_xor_sync(0xffffffffu, act1, 1);  // o (on evens)

        const int nxt = cur ^ 1;
        if (p == 0) {
            // act0 = i, act1 = f, x0 = g, x1 = o
            c = act1 * c + act0 * x0;
            float hv = x1 * fast_tanh(c);
            hbuf[nxt * HID + j] = hv;
            hout[(size_t)s * HID + j] = hv;         // off critical path
        }
        __syncthreads();

        p0 = p0n; p1 = p1n;
    }
}

// ============================================================================
// Input projection: g_pre[t, r] = (ba[r] + bb[r]) + sum_k A[t,k] * W[r,k]
// ============================================================================
template <int K>
__global__ void __launch_bounds__(512)
addmm_kernel(const float* __restrict__ Aext, int useH1,
             const float* __restrict__ W,
             const float* __restrict__ ba, const float* __restrict__ bb)
{
    constexpr int BT = 8;
    const float* __restrict__ A = useH1 ? g_h1 : Aext;
    __shared__ float As[BT * K];

    const int t0 = blockIdx.x * BT;
    for (int idx = threadIdx.x; idx < BT * K; idx += 512)
        As[idx] = A[(size_t)t0 * K + idx];
    __syncthreads();

    const int r = threadIdx.x;
    float bias = ba[r] + bb[r];
    float acc[BT];
#pragma unroll
    for (int i = 0; i < BT; i++) acc[i] = bias;

    const float* wr = W + (size_t)r * K;
#pragma unroll 2
    for (int k = 0; k < K; k++) {
        float wv = __ldg(wr + k);
#pragma unroll
        for (int i = 0; i < BT; i++) acc[i] = fmaf(wv, As[i * K + k], acc[i]);
    }
#pragma unroll
    for (int i = 0; i < BT; i++)
        g_pre[(size_t)(t0 + i) * GROWS + r] = acc[i];
}

// ============================================================================
// Final FC: out[t, o] = fc_b[o] + sum_k g_h2[t,k] * fc_W[o,k]   (OUT = 5)
// ============================================================================
__global__ void __launch_bounds__(256)
fc_kernel(const float* __restrict__ fcW, const float* __restrict__ fcb,
          float* __restrict__ out)
{
    __shared__ float Ws[5 * HID];
    __shared__ float bs[5];
    for (int idx = threadIdx.x; idx < 5 * HID; idx += 256) Ws[idx] = fcW[idx];
    if (threadIdx.x < 5) bs[threadIdx.x] = fcb[threadIdx.x];
    __syncthreads();

    const int t = blockIdx.x * 256 + threadIdx.x;
    float acc[5];
#pragma unroll
    for (int o = 0; o < 5; o++) acc[o] = bs[o];

    const float4* hp = reinterpret_cast<const float4*>(&g_h2[(size_t)t * HID]);
#pragma unroll 4
    for (int k4 = 0; k4 < HID / 4; k4++) {
        float4 h = hp[k4];
#pragma unroll
        for (int o = 0; o < 5; o++) {
            acc[o] = fmaf(h.x, Ws[o * HID + 4 * k4 + 0], acc[o]);
            acc[o] = fmaf(h.y, Ws[o * HID + 4 * k4 + 1], acc[o]);
            acc[o] = fmaf(h.z, Ws[o * HID + 4 * k4 + 2], acc[o]);
            acc[o] = fmaf(h.w, Ws[o * HID + 4 * k4 + 3], acc[o]);
        }
    }
#pragma unroll
    for (int o = 0; o < 5; o++) out[(size_t)t * 5 + o] = acc[o];
}

// ============================================================================
// kernel_launch: pre1 GEMM -> scan L1 -> pre2 GEMM -> scan L2 -> FC
// ============================================================================
extern "C" void kernel_launch(void* const* d_in, const int* in_sizes, int n_in,
                              void* d_out, int out_size)
{
    (void)in_sizes; (void)n_in; (void)out_size;

    const float* x     = (const float*)d_in[0];
    const float* W_ih1 = (const float*)d_in[1];
    const float* W_hh1 = (const float*)d_in[2];
    const float* b_ih1 = (const float*)d_in[3];
    const float* b_hh1 = (const float*)d_in[4];
    const float* W_ih2 = (const float*)d_in[5];
    const float* W_hh2 = (const float*)d_in[6];
    const float* b_ih2 = (const float*)d_in[7];
    const float* b_hh2 = (const float*)d_in[8];
    const float* fc_W  = (const float*)d_in[9];
    const float* fc_b  = (const float*)d_in[10];
    float* out = (float*)d_out;

    // scan kernel needs 64KB (WQ) + 1KB (h) dynamic smem
    const int scan_smem = GROWS * CS * 4 + 2 * HID * 4;
    cudaFuncSetAttribute(lstm_scan_kernel,
                         cudaFuncAttributeMaxDynamicSharedMemorySize, scan_smem);

    addmm_kernel<50><<<TSEQ / 8, 512>>>(x, 0, W_ih1, b_ih1, b_hh1);
    lstm_scan_kernel<<<1, 256, scan_smem>>>(W_hh1, 0);
    addmm_kernel<128><<<TSEQ / 8, 512>>>(nullptr, 1, W_ih2, b_ih2, b_hh2);
    lstm_scan_kernel<<<1, 256, scan_smem>>>(W_hh2, 1);
    fc_kernel<<<TSEQ / 256, 256>>>(fc_W, fc_b, out);
}

// round 6
// speedup vs baseline: 1.7693x; 1.1585x over previous
#include <cuda_runtime.h>
#include <cstdint>

typedef unsigned long long u64;

// ---------------- problem constants ----------------
#define TSEQ 16384
#define HID  128
#define GROWS 512   // 4*HID

// ---------------- scratch (device globals; no allocation) ----------------
__device__ float g_pre[(size_t)TSEQ * GROWS];
__device__ float g_h1[(size_t)TSEQ * HID];
__device__ float g_h2[(size_t)TSEQ * HID];

// ---------------- helpers ----------------
__device__ __forceinline__ uint32_t smem_u32(const void* p) {
    return (uint32_t)__cvta_generic_to_shared(p);
}
__device__ __forceinline__ u64 ffma2(u64 a, u64 b, u64 c) {
    u64 d;
    asm("fma.rn.f32x2 %0, %1, %2, %3;" : "=l"(d) : "l"(a), "l"(b), "l"(c));
    return d;
}
__device__ __forceinline__ u64 fadd2(u64 a, u64 b) {
    u64 d;
    asm("add.rn.f32x2 %0, %1, %2;" : "=l"(d) : "l"(a), "l"(b));
    return d;
}
__device__ __forceinline__ float2 unpack2(u64 a) {
    float2 r;
    asm("mov.b64 {%0, %1}, %2;" : "=f"(r.x), "=f"(r.y) : "l"(a));
    return r;
}
__device__ __forceinline__ float fast_sigmoid(float x) {
    return __fdividef(1.f, 1.f + __expf(-x));
}
__device__ __forceinline__ float fast_tanh(float x) {
    return 1.f - __fdividef(2.f, __expf(2.f * x) + 1.f);
}
__device__ __forceinline__ void mbar_wait_cluster(uint32_t addr, unsigned parity) {
    asm volatile(
        "{\n\t"
        ".reg .pred P1;\n\t"
        "WAIT_%=:\n\t"
        "mbarrier.try_wait.parity.acquire.cluster.shared::cta.b64 P1, [%0], %1, 0x989680;\n\t"
        "@P1 bra DONE_%=;\n\t"
        "bra WAIT_%=;\n\t"
        "DONE_%=:\n\t"
        "}"
        :: "r"(addr), "r"(parity) : "memory");
}

// ============================================================================
// LSTM scan: 2-CTA cluster, 256 threads/CTA, all 128 weight cols in regs.
// CTA rank r owns units j in [64r, 64r+64).
// Thread map: lane = 4*(unit%8) + gate ; warp = unit/8
//   -> the 4 gates of a unit sit in adjacent lanes (shfl combine).
// Per step s:
//   1. local-half matvec on lh[s&3]  (peer h still in flight)
//   2. wait bar_rem[s&3]             (peer's 64 owner-arrivals)
//   3. remote-half matvec on rh[s&3]
//   4. activation + 3 shfls -> owner lane (gate 0)
//   5. owner: c,h update; st.shared::cluster h -> peer rh[(s+1)&3] +
//      arrive.release.cluster on peer bar_rem[(s+1)&3]; write lh[(s+1)&3];
//      stream h to global
//   6. __syncthreads (publishes lh locally; certifies all local reads —
//      transitively gates the peer's ring rewrite 2+ steps later)
// Ring-reuse safety: A overwrites B's rh[b] (h_{s+1}, at A's step s) only
// after passing its stage-2 wait of step s, which needs B's arrivals sent at
// the end of B's step s-1; B's read of rh[b]'s old value (h_{s-3}) happened
// at B's step s-3, >=2 __syncthreads earlier. Release/acquire chain orders it.
// ============================================================================
__global__ void __cluster_dims__(2, 1, 1) __launch_bounds__(256, 1)
lstm_scan_kernel(const float* __restrict__ W_hh, int layer)
{
    __shared__ __align__(16) float lh[4][64];   // h of locally-owned units
    __shared__ __align__(16) float rh[4][64];   // h of peer-owned units
    __shared__ __align__(8) u64 bar_rem[4];

    const float* __restrict__ pre = g_pre;
    float* __restrict__ hout = layer ? g_h2 : g_h1;

    const int tid  = threadIdx.x;
    const int lane = tid & 31;
    const int warp = tid >> 5;
    unsigned rank;
    asm("mov.u32 %0, %%cluster_ctarank;" : "=r"(rank));
    const unsigned peer = rank ^ 1u;

    const int gate = lane & 3;                 // 0..3 = i,f,g,o
    const int uc   = warp * 8 + (lane >> 2);   // unit within CTA [0,64)
    const int j    = (int)rank * 64 + uc;      // global hidden unit
    const int row  = gate * HID + j;           // gate row [0,512)

    // ---- weights: local half = cols [64*rank, +64), remote half = other 64
    u64 wl[32], wr_[32];
    {
        const ulonglong2* wsl = reinterpret_cast<const ulonglong2*>(
            W_hh + (size_t)row * HID + 64 * rank);
        const ulonglong2* wsr = reinterpret_cast<const ulonglong2*>(
            W_hh + (size_t)row * HID + 64 * peer);
#pragma unroll
        for (int i = 0; i < 16; i++) {
            ulonglong2 a = wsl[i];
            wl[2 * i] = a.x; wl[2 * i + 1] = a.y;
            ulonglong2 b = wsr[i];
            wr_[2 * i] = b.x; wr_[2 * i + 1] = b.y;
        }
    }

    // ---- init ring slot 0 (h_0 = 0) and barriers
    if (tid < 64) {
#pragma unroll
        for (int b = 0; b < 4; b++) { lh[b][tid] = 0.f; rh[b][tid] = 0.f; }
    }
    const uint32_t barb = smem_u32(bar_rem);
    if (tid == 0) {
#pragma unroll
        for (int b = 0; b < 4; b++)
            asm volatile("mbarrier.init.shared.b64 [%0], %1;"
                         :: "r"(barb + (unsigned)(b * 8)), "r"(64u));
        // pre-complete slot 0 phase 0 (step-0 input is the zero state)
        asm volatile("mbarrier.arrive.shared::cta.b64 _, [%0], %1;"
                     :: "r"(barb), "r"(64u) : "memory");
        asm volatile("fence.mbarrier_init.release.cluster;" ::: "memory");
    }
    __syncthreads();
    asm volatile("barrier.cluster.arrive.aligned;" ::: "memory");
    asm volatile("barrier.cluster.wait.aligned;"   ::: "memory");

    // peer addresses
    uint32_t peer_rh, peer_bar;
    asm("mapa.shared::cluster.u32 %0, %1, %2;"
        : "=r"(peer_rh) : "r"(smem_u32(rh)), "r"(peer));
    asm("mapa.shared::cluster.u32 %0, %1, %2;"
        : "=r"(peer_bar) : "r"(barb), "r"(peer));

    float c = 0.f;                          // cell state (owner lanes, gate 0)
    float pcur = pre[row];                  // pre for step 0
    float pnext = pre[GROWS + row];         // pre for step 1

    for (int s = 0; s < TSEQ; s++) {
        // prefetch pre for s+2 (LDG latency hidden under ~2 steps)
        float pfut = 0.f;
        if (s + 2 < TSEQ) pfut = pre[(size_t)(s + 2) * GROWS + row];

        const int buf = s & 3;
        const unsigned ph = (unsigned)((s >> 2) & 1);

        // ---- 1. local-half matvec (peer data still in flight)
        u64 a0 = 0ull, a1 = 0ull, a2 = 0ull, a3 = 0ull;
        {
            const ulonglong2* hp = reinterpret_cast<const ulonglong2*>(lh[buf]);
#pragma unroll
            for (int i = 0; i < 16; i += 2) {   // 16 x ulonglong2 = 64 floats
                ulonglong2 x = hp[i];
                ulonglong2 y = hp[i + 1];
                a0 = ffma2(wl[2 * i],     x.x, a0);
                a1 = ffma2(wl[2 * i + 1], x.y, a1);
                a2 = ffma2(wl[2 * i + 2], y.x, a2);
                a3 = ffma2(wl[2 * i + 3], y.y, a3);
            }
        }

        // ---- 2. wait for peer's h-half
        mbar_wait_cluster(barb + (unsigned)(buf * 8), ph);

        // ---- 3. remote-half matvec
        {
            const ulonglong2* hp = reinterpret_cast<const ulonglong2*>(rh[buf]);
#pragma unroll
            for (int i = 0; i < 16; i += 2) {
                ulonglong2 x = hp[i];
                ulonglong2 y = hp[i + 1];
                a0 = ffma2(wr_[2 * i],     x.x, a0);
                a1 = ffma2(wr_[2 * i + 1], x.y, a1);
                a2 = ffma2(wr_[2 * i + 2], y.x, a2);
                a3 = ffma2(wr_[2 * i + 3], y.y, a3);
            }
        }
        float2 sm2 = unpack2(fadd2(fadd2(a0, a1), fadd2(a2, a3)));
        float gval = sm2.x + sm2.y + pcur;

        // ---- 4. activation + gather gates to owner lane (gate 0)
        float av = (gate == 2) ? fast_tanh(gval) : fast_sigmoid(gval);
        const unsigned bl = (unsigned)(lane & ~3);
        float fv = __shfl_sync(0xffffffffu, av, bl + 1);
        float gv = __shfl_sync(0xffffffffu, av, bl + 2);
        float ov = __shfl_sync(0xffffffffu, av, bl + 3);

        // ---- 5. owner epilogue: update state, send h
        const int nbuf = (s + 1) & 3;
        if (gate == 0) {
            c = fv * c + av * gv;
            float hv = ov * fast_tanh(c);

            // remote first: longest-latency op starts earliest
            const unsigned roff = (unsigned)((nbuf * 64 + uc) * 4);
            asm volatile("st.shared::cluster.f32 [%0], %1;"
                         :: "r"(peer_rh + roff), "f"(hv) : "memory");
            asm volatile(
                "mbarrier.arrive.release.cluster.shared::cluster.b64 _, [%0];"
                :: "r"(peer_bar + (unsigned)(nbuf * 8)) : "memory");

            lh[nbuf][uc] = hv;
            hout[(size_t)s * HID + j] = hv;   // off critical path
        }

        // ---- 6. publish lh locally + certify local reads of slot `buf`
        __syncthreads();

        pcur = pnext;
        pnext = pfut;
    }

    asm volatile("barrier.cluster.arrive.aligned;" ::: "memory");
    asm volatile("barrier.cluster.wait.aligned;"   ::: "memory");
}

// ============================================================================
// Input projection: g_pre[t, r] = (ba[r] + bb[r]) + sum_k A[t,k] * W[r,k]
// ============================================================================
template <int K>
__global__ void __launch_bounds__(512)
addmm_kernel(const float* __restrict__ Aext, int useH1,
             const float* __restrict__ W,
             const float* __restrict__ ba, const float* __restrict__ bb)
{
    constexpr int BT = 8;
    const float* __restrict__ A = useH1 ? g_h1 : Aext;
    __shared__ float As[BT * K];

    const int t0 = blockIdx.x * BT;
    for (int idx = threadIdx.x; idx < BT * K; idx += 512)
        As[idx] = A[(size_t)t0 * K + idx];
    __syncthreads();

    const int r = threadIdx.x;
    float bias = ba[r] + bb[r];
    float acc[BT];
#pragma unroll
    for (int i = 0; i < BT; i++) acc[i] = bias;

    const float* wr = W + (size_t)r * K;
#pragma unroll 2
    for (int k = 0; k < K; k++) {
        float wv = __ldg(wr + k);
#pragma unroll
        for (int i = 0; i < BT; i++) acc[i] = fmaf(wv, As[i * K + k], acc[i]);
    }
#pragma unroll
    for (int i = 0; i < BT; i++)
        g_pre[(size_t)(t0 + i) * GROWS + r] = acc[i];
}

// ============================================================================
// Final FC: out[t, o] = fc_b[o] + sum_k g_h2[t,k] * fc_W[o,k]   (OUT = 5)
// ============================================================================
__global__ void __launch_bounds__(256)
fc_kernel(const float* __restrict__ fcW, const float* __restrict__ fcb,
          float* __restrict__ out)
{
    __shared__ float Ws[5 * HID];
    __shared__ float bs[5];
    for (int idx = threadIdx.x; idx < 5 * HID; idx += 256) Ws[idx] = fcW[idx];
    if (threadIdx.x < 5) bs[threadIdx.x] = fcb[threadIdx.x];
    __syncthreads();

    const int t = blockIdx.x * 256 + threadIdx.x;
    float acc[5];
#pragma unroll
    for (int o = 0; o < 5; o++) acc[o] = bs[o];

    const float4* hp = reinterpret_cast<const float4*>(&g_h2[(size_t)t * HID]);
#pragma unroll 4
    for (int k4 = 0; k4 < HID / 4; k4++) {
        float4 h = hp[k4];
#pragma unroll
        for (int o = 0; o < 5; o++) {
            acc[o] = fmaf(h.x, Ws[o * HID + 4 * k4 + 0], acc[o]);
            acc[o] = fmaf(h.y, Ws[o * HID + 4 * k4 + 1], acc[o]);
            acc[o] = fmaf(h.z, Ws[o * HID + 4 * k4 + 2], acc[o]);
            acc[o] = fmaf(h.w, Ws[o * HID + 4 * k4 + 3], acc[o]);
        }
    }
#pragma unroll
    for (int o = 0; o < 5; o++) out[(size_t)t * 5 + o] = acc[o];
}

// ============================================================================
// kernel_launch: pre1 GEMM -> scan L1 -> pre2 GEMM -> scan L2 -> FC
// ============================================================================
extern "C" void kernel_launch(void* const* d_in, const int* in_sizes, int n_in,
                              void* d_out, int out_size)
{
    (void)in_sizes; (void)n_in; (void)out_size;

    const float* x     = (const float*)d_in[0];
    const float* W_ih1 = (const float*)d_in[1];
    const float* W_hh1 = (const float*)d_in[2];
    const float* b_ih1 = (const float*)d_in[3];
    const float* b_hh1 = (const float*)d_in[4];
    const float* W_ih2 = (const float*)d_in[5];
    const float* W_hh2 = (const float*)d_in[6];
    const float* b_ih2 = (const float*)d_in[7];
    const float* b_hh2 = (const float*)d_in[8];
    const float* fc_W  = (const float*)d_in[9];
    const float* fc_b  = (const float*)d_in[10];
    float* out = (float*)d_out;

    addmm_kernel<50><<<TSEQ / 8, 512>>>(x, 0, W_ih1, b_ih1, b_hh1);
    lstm_scan_kernel<<<2, 256>>>(W_hh1, 0);
    addmm_kernel<128><<<TSEQ / 8, 512>>>(nullptr, 1, W_ih2, b_ih2, b_hh2);
    lstm_scan_kernel<<<2, 256>>>(W_hh2, 1);
    fc_kernel<<<TSEQ / 256, 256>>>(fc_W, fc_b, out);
}